// round 2
// baseline (speedup 1.0000x reference)
#include <cuda_runtime.h>

#define NMAX 100000
#define EMAX 3200000
#define FIN  512
#define HID  16
#define SCAN_BS 1024
#define SCAN_NBMAX 128

// ---------------- scratch (static device globals; no allocs) ----------------
__device__ float d_deg [NMAX];          // degree (incl self-loop)
__device__ float d_dinv[NMAX];          // deg^-1/2
__device__ float d_h1p [NMAX * HID];    // h1 * dinv[src]  (pre-scaled messages)
__device__ float d_gp  [NMAX];          // g * dinv[src] for layer 2
__device__ int   d_rs  [NMAX];          // CSR row starts (by dst)
__device__ int   d_next[NMAX];          // fill cursors
__device__ int   d_csr [EMAX];          // src ids grouped by dst
__device__ int   d_bsum[SCAN_NBMAX];
__device__ int   d_boff[SCAN_NBMAX];

// ---------------- kernels ----------------
__global__ void k_init(int N) {
    int i = blockIdx.x * blockDim.x + threadIdx.x;
    if (i < N) d_deg[i] = 1.0f;         // self-loop
}

// degree histogram (vectorized index loads)
__global__ void k_deg(const int* __restrict__ dst, int E) {
    int t = blockIdx.x * blockDim.x + threadIdx.x;
    int e4 = t * 4;
    if (e4 + 3 < E) {
        int4 d = ((const int4*)dst)[t];
        atomicAdd(&d_deg[d.x], 1.0f);
        atomicAdd(&d_deg[d.y], 1.0f);
        atomicAdd(&d_deg[d.z], 1.0f);
        atomicAdd(&d_deg[d.w], 1.0f);
    } else {
        for (int e = e4; e < E; e++) atomicAdd(&d_deg[dst[e]], 1.0f);
    }
}

// ---- scan of edge counts (deg-1) -> CSR row starts ----
__global__ void __launch_bounds__(SCAN_BS) k_scanA(int N) {
    int i = blockIdx.x * SCAN_BS + threadIdx.x;
    int lane = threadIdx.x & 31, w = threadIdx.x >> 5;
    int c = (i < N) ? ((int)d_deg[i] - 1) : 0;
    int v = c;
    #pragma unroll
    for (int off = 1; off < 32; off <<= 1) {
        int n = __shfl_up_sync(0xffffffffu, v, off);
        if (lane >= off) v += n;
    }
    __shared__ int ws[32];
    if (lane == 31) ws[w] = v;
    __syncthreads();
    if (w == 0) {
        int s = ws[lane];
        #pragma unroll
        for (int off = 1; off < 32; off <<= 1) {
            int n = __shfl_up_sync(0xffffffffu, s, off);
            if (lane >= off) s += n;
        }
        ws[lane] = s;
    }
    __syncthreads();
    int add = w ? ws[w - 1] : 0;
    if (i < N) d_rs[i] = add + v - c;                     // exclusive in block
    if (threadIdx.x == SCAN_BS - 1) d_bsum[blockIdx.x] = add + v;
}

__global__ void k_scanB(int NB) {
    int t = threadIdx.x;            // 128 threads
    int lane = t & 31, w = t >> 5;
    int c = (t < NB) ? d_bsum[t] : 0;
    int v = c;
    #pragma unroll
    for (int off = 1; off < 32; off <<= 1) {
        int n = __shfl_up_sync(0xffffffffu, v, off);
        if (lane >= off) v += n;
    }
    __shared__ int ws[4];
    if (lane == 31) ws[w] = v;
    __syncthreads();
    int add = 0;
    for (int k = 0; k < w; k++) add += ws[k];
    if (t < NB) d_boff[t] = add + v - c;                  // exclusive
}

__global__ void k_scanC(int N) {
    int i = blockIdx.x * blockDim.x + threadIdx.x;
    if (i >= N) return;
    int r = d_rs[i] + d_boff[i >> 10];
    d_rs[i]   = r;
    d_next[i] = r;
}

// scatter edges into CSR slots (counting sort by dst)
__global__ void k_fill(const int* __restrict__ ei, int E) {
    int t = blockIdx.x * blockDim.x + threadIdx.x;
    int e4 = t * 4;
    if (e4 + 3 < E) {
        int4 s = ((const int4*)ei)[t];
        int4 d = ((const int4*)(ei + E))[t];
        d_csr[atomicAdd(&d_next[d.x], 1)] = s.x;
        d_csr[atomicAdd(&d_next[d.y], 1)] = s.y;
        d_csr[atomicAdd(&d_next[d.z], 1)] = s.z;
        d_csr[atomicAdd(&d_next[d.w], 1)] = s.w;
    } else {
        for (int e = e4; e < E; e++)
            d_csr[atomicAdd(&d_next[ei[E + e]], 1)] = ei[e];
    }
}

// GEMM1: h1 = x @ W1; dinv = rsqrt(deg); h1' = h1*dinv (pre-scaled message).
__global__ void __launch_bounds__(256) k_gemm(const float* __restrict__ x,
                                              const float* __restrict__ W1,
                                              int N) {
    extern __shared__ float sm[];
    float* Ws = sm;                  // FIN*HID = 8192 floats
    float* xs = sm + FIN * HID;      // 256 * 33 floats
    int tid = threadIdx.x;

    {
        const float4* W4 = (const float4*)W1;
        float4*       Wd = (float4*)Ws;
        #pragma unroll
        for (int i = 0; i < (FIN * HID / 4) / 256; i++)
            Wd[tid + i * 256] = W4[tid + i * 256];
    }

    int row = blockIdx.x * 256 + tid;
    unsigned long long acc[HID / 2];
    #pragma unroll
    for (int j = 0; j < HID / 2; j++) acc[j] = 0ull;

    for (int kt = 0; kt < FIN / 32; kt++) {
        __syncthreads();
        #pragma unroll
        for (int i = 0; i < 8; i++) {
            int fid = tid + i * 256;
            int r = fid >> 3, c4 = fid & 7;
            int gr = blockIdx.x * 256 + r;
            float4 v = make_float4(0.f, 0.f, 0.f, 0.f);
            if (gr < N)
                v = ((const float4*)x)[(size_t)gr * (FIN / 4) + kt * 8 + c4];
            float* dp = &xs[r * 33 + c4 * 4];
            dp[0] = v.x; dp[1] = v.y; dp[2] = v.z; dp[3] = v.w;
        }
        __syncthreads();

        const ulonglong2* Wp = (const ulonglong2*)(Ws + (size_t)kt * 32 * HID);
        #pragma unroll
        for (int c = 0; c < 32; c++) {
            float xv = xs[tid * 33 + c];
            unsigned long long x2;
            asm("mov.b64 %0,{%1,%1};" : "=l"(x2) : "f"(xv));
            #pragma unroll
            for (int j = 0; j < 4; j++) {
                ulonglong2 w = Wp[c * 4 + j];
                asm("fma.rn.f32x2 %0,%1,%2,%0;" : "+l"(acc[2*j])   : "l"(x2), "l"(w.x));
                asm("fma.rn.f32x2 %0,%1,%2,%0;" : "+l"(acc[2*j+1]) : "l"(x2), "l"(w.y));
            }
        }
    }

    if (row < N) {
        float dv = rsqrtf(d_deg[row]);
        d_dinv[row] = dv;
        float4* hp = (float4*)(d_h1p + (size_t)row * HID);
        #pragma unroll
        for (int j = 0; j < HID / 2; j++) {
            float lo, hi;
            asm("mov.b64 {%0,%1},%2;" : "=f"(lo), "=f"(hi) : "l"(acc[j]));
            ((float*)hp)[2*j]   = lo * dv;
            ((float*)hp)[2*j+1] = hi * dv;
        }
    }
}

// Layer-1 aggregation + fused layer-2 MLP. One warp per node.
// 4 lanes per edge (one float4 each) -> 1 gather wavefront per edge, no atomics.
// gp[i] = dinv_i * sum_h( relu(dinv_i*(self+sum_nbr h1p) + b1) * W2 )
__global__ void __launch_bounds__(256) k_agg1(const float* __restrict__ b1,
                                              const float* __restrict__ W2,
                                              int N) {
    int warp = (blockIdx.x * blockDim.x + threadIdx.x) >> 5;
    if (warp >= N) return;
    int lane = threadIdx.x & 31;
    int base = d_rs[warp];
    int end  = base + ((int)__ldg(&d_deg[warp]) - 1);
    int p = lane & 3;

    float4 acc = make_float4(0.f, 0.f, 0.f, 0.f);
    for (int it = base + (lane >> 2); it < end; it += 8) {
        int s = __ldg(&d_csr[it]);
        float4 v = __ldg(&((const float4*)d_h1p)[s * 4 + p]);
        acc.x += v.x; acc.y += v.y; acc.z += v.z; acc.w += v.w;
    }
    __syncwarp();
    #pragma unroll
    for (int off = 16; off >= 4; off >>= 1) {
        acc.x += __shfl_down_sync(0xffffffffu, acc.x, off);
        acc.y += __shfl_down_sync(0xffffffffu, acc.y, off);
        acc.z += __shfl_down_sync(0xffffffffu, acc.z, off);
        acc.w += __shfl_down_sync(0xffffffffu, acc.w, off);
    }
    if (lane < 4) {
        float dv = d_dinv[warp];
        float4 self = ((const float4*)d_h1p)[warp * 4 + lane];
        acc.x += self.x; acc.y += self.y; acc.z += self.z; acc.w += self.w;
        float4 bb = __ldg(&((const float4*)b1)[lane]);
        float4 w  = __ldg(&((const float4*)W2)[lane]);
        float g = fmaxf(fmaf(dv, acc.x, bb.x), 0.f) * w.x
                + fmaxf(fmaf(dv, acc.y, bb.y), 0.f) * w.y
                + fmaxf(fmaf(dv, acc.z, bb.z), 0.f) * w.z
                + fmaxf(fmaf(dv, acc.w, bb.w), 0.f) * w.w;
        g += __shfl_xor_sync(0xfu, g, 1);
        g += __shfl_xor_sync(0xfu, g, 2);
        if (lane == 0) d_gp[warp] = g * dv;
    }
}

// Layer-2 aggregation + sigmoid. One warp per node, scalar gathers, no atomics.
__global__ void __launch_bounds__(256) k_agg2(const float* __restrict__ b2,
                                              float* __restrict__ out, int N) {
    int warp = (blockIdx.x * blockDim.x + threadIdx.x) >> 5;
    if (warp >= N) return;
    int lane = threadIdx.x & 31;
    int base = d_rs[warp];
    int end  = base + ((int)__ldg(&d_deg[warp]) - 1);

    float sum = 0.f;
    for (int j = base + lane; j < end; j += 32)
        sum += __ldg(&d_gp[__ldg(&d_csr[j])]);
    __syncwarp();
    #pragma unroll
    for (int off = 16; off >= 1; off >>= 1)
        sum += __shfl_down_sync(0xffffffffu, sum, off);
    if (lane == 0) {
        float dv = d_dinv[warp];
        float z = fmaf(dv, sum + d_gp[warp], __ldg(&b2[0]));
        out[warp] = 1.f / (1.f + __expf(-z));
    }
}

// ---------------- launch ----------------
extern "C" void kernel_launch(void* const* d_in, const int* in_sizes, int n_in,
                              void* d_out, int out_size) {
    const float* x  = (const float*)d_in[0];
    const float* W1 = (const float*)d_in[1];
    const float* b1 = (const float*)d_in[2];
    const float* W2 = (const float*)d_in[3];
    const float* b2 = (const float*)d_in[4];
    const int*   ei = (const int*)d_in[5];

    int N = in_sizes[0] / FIN;     // 100000
    int E = in_sizes[5] / 2;       // 3200000
    int NB = (N + SCAN_BS - 1) / SCAN_BS;

    // one-time host resources (created on the pre-capture correctness call)
    static cudaStream_t s2 = nullptr;
    static cudaEvent_t evA = nullptr, evB = nullptr;
    if (!s2) {
        cudaStreamCreateWithFlags(&s2, cudaStreamNonBlocking);
        cudaEventCreateWithFlags(&evA, cudaEventDisableTiming);
        cudaEventCreateWithFlags(&evB, cudaEventDisableTiming);
        const int SMEM_BYTES = (FIN * HID + 256 * 33) * (int)sizeof(float);
        cudaFuncSetAttribute(k_gemm, cudaFuncAttributeMaxDynamicSharedMemorySize,
                             SMEM_BYTES);
    }
    const int SMEM_BYTES = (FIN * HID + 256 * 33) * (int)sizeof(float); // 66560

    // main stream: degree
    k_init<<<(N + 255) / 256, 256>>>(N);
    k_deg <<<((E / 4) + 255) / 256, 256>>>(ei + E, E);

    // fork: GEMM (needs deg only) runs concurrent with CSR build
    cudaEventRecord(evA, 0);
    cudaStreamWaitEvent(s2, evA, 0);
    k_gemm<<<(N + 255) / 256, 256, SMEM_BYTES, s2>>>(x, W1, N);
    cudaEventRecord(evB, s2);

    // main stream: CSR build
    k_scanA<<<NB, SCAN_BS>>>(N);
    k_scanB<<<1, 128>>>(NB);
    k_scanC<<<(N + 255) / 256, 256>>>(N);
    k_fill <<<((E / 4) + 255) / 256, 256>>>(ei, E);

    // join, then aggregate
    cudaStreamWaitEvent(0, evB, 0);
    k_agg1<<<(N * 32 + 255) / 256, 256>>>(b1, W2, N);
    k_agg2<<<(N * 32 + 255) / 256, 256>>>(b2, (float*)d_out, N);
}

// round 3
// speedup vs baseline: 1.0292x; 1.0292x over previous
#include <cuda_runtime.h>

#define NMAX 100000
#define EMAX 3200000
#define FIN  512
#define HID  16
#define SCAN_BS 1024
#define SCAN_NBMAX 128

// ---------------- scratch (static device globals; no allocs) ----------------
__device__ int   d_cnt [NMAX];          // edge count per dst (excl self-loop)
__device__ float d_dinv[NMAX];          // (deg+1)^-1/2
__device__ float d_h1p [NMAX * HID];    // h1 (then scaled by dinv[src])
__device__ float d_gp  [NMAX];          // g * dinv[src] for layer 2
__device__ int   d_rs  [NMAX];          // CSR row starts (by dst)
__device__ int   d_next[NMAX];          // fill cursors
__device__ int   d_csr [EMAX];          // src ids grouped by dst
__device__ int   d_bsum[SCAN_NBMAX];

// ---------------- kernels ----------------
__global__ void k_zero(int N) {
    int i = blockIdx.x * blockDim.x + threadIdx.x;
    if (i < N) d_cnt[i] = 0;
}

// degree histogram (int atomics -> REDG, vectorized index loads)
__global__ void k_deg(const int* __restrict__ dst, int E) {
    int t = blockIdx.x * blockDim.x + threadIdx.x;
    int e4 = t * 4;
    if (e4 + 3 < E) {
        int4 d = __ldg(&((const int4*)dst)[t]);
        atomicAdd(&d_cnt[d.x], 1);
        atomicAdd(&d_cnt[d.y], 1);
        atomicAdd(&d_cnt[d.z], 1);
        atomicAdd(&d_cnt[d.w], 1);
    } else {
        for (int e = e4; e < E; e++) atomicAdd(&d_cnt[dst[e]], 1);
    }
}

// block-level exclusive scan of d_cnt -> d_rs (partial) + per-block sums
__global__ void __launch_bounds__(SCAN_BS) k_scanA(int N) {
    int i = blockIdx.x * SCAN_BS + threadIdx.x;
    int lane = threadIdx.x & 31, w = threadIdx.x >> 5;
    int c = (i < N) ? d_cnt[i] : 0;
    int v = c;
    #pragma unroll
    for (int off = 1; off < 32; off <<= 1) {
        int n = __shfl_up_sync(0xffffffffu, v, off);
        if (lane >= off) v += n;
    }
    __shared__ int ws[32];
    if (lane == 31) ws[w] = v;
    __syncthreads();
    if (w == 0) {
        int s = ws[lane];
        #pragma unroll
        for (int off = 1; off < 32; off <<= 1) {
            int n = __shfl_up_sync(0xffffffffu, s, off);
            if (lane >= off) s += n;
        }
        ws[lane] = s;
    }
    __syncthreads();
    int add = w ? ws[w - 1] : 0;
    if (i < N) d_rs[i] = add + v - c;                     // exclusive in block
    if (threadIdx.x == SCAN_BS - 1) d_bsum[blockIdx.x] = add + v;
}

// fuse scanB+scanC: each 256-block adds prefix of bsum[0..nb) and sets dinv.
// nb = blockIdx>>2 is constant within a block (256 | 1024).
__global__ void __launch_bounds__(256) k_scanFix(int N) {
    __shared__ int wsum[8];
    __shared__ int s_off;
    int t = threadIdx.x;
    int nb = blockIdx.x >> 2;
    int v = (t < nb && t < SCAN_NBMAX) ? d_bsum[t] : 0;
    #pragma unroll
    for (int off = 16; off >= 1; off >>= 1)
        v += __shfl_down_sync(0xffffffffu, v, off);
    if ((t & 31) == 0) wsum[t >> 5] = v;
    __syncthreads();
    if (t == 0) {
        int s = 0;
        #pragma unroll
        for (int k = 0; k < 8; k++) s += wsum[k];
        s_off = s;
    }
    __syncthreads();
    int i = blockIdx.x * 256 + t;
    if (i < N) {
        int r = d_rs[i] + s_off;
        d_rs[i]   = r;
        d_next[i] = r;
        d_dinv[i] = rsqrtf((float)(d_cnt[i] + 1));
    }
}

// scatter edges into CSR slots (counting sort by dst)
__global__ void k_fill(const int* __restrict__ ei, int E) {
    int t = blockIdx.x * blockDim.x + threadIdx.x;
    int e4 = t * 4;
    if (e4 + 3 < E) {
        int4 s = __ldg(&((const int4*)ei)[t]);
        int4 d = __ldg(&((const int4*)(ei + E))[t]);
        d_csr[atomicAdd(&d_next[d.x], 1)] = s.x;
        d_csr[atomicAdd(&d_next[d.y], 1)] = s.y;
        d_csr[atomicAdd(&d_next[d.z], 1)] = s.z;
        d_csr[atomicAdd(&d_next[d.w], 1)] = s.w;
    } else {
        for (int e = e4; e < E; e++)
            d_csr[atomicAdd(&d_next[ei[E + e]], 1)] = ei[e];
    }
}

// GEMM1: h1 = x @ W1 (UNSCALED -> no dependency on graph side).
__global__ void __launch_bounds__(256) k_gemm(const float* __restrict__ x,
                                              const float* __restrict__ W1,
                                              int N) {
    extern __shared__ float sm[];
    float* Ws = sm;                  // FIN*HID = 8192 floats
    float* xs = sm + FIN * HID;      // 256 * 33 floats
    int tid = threadIdx.x;

    {
        const float4* W4 = (const float4*)W1;
        float4*       Wd = (float4*)Ws;
        #pragma unroll
        for (int i = 0; i < (FIN * HID / 4) / 256; i++)
            Wd[tid + i * 256] = W4[tid + i * 256];
    }

    int row = blockIdx.x * 256 + tid;
    unsigned long long acc[HID / 2];
    #pragma unroll
    for (int j = 0; j < HID / 2; j++) acc[j] = 0ull;

    for (int kt = 0; kt < FIN / 32; kt++) {
        __syncthreads();
        #pragma unroll
        for (int i = 0; i < 8; i++) {
            int fid = tid + i * 256;
            int r = fid >> 3, c4 = fid & 7;
            int gr = blockIdx.x * 256 + r;
            float4 v = make_float4(0.f, 0.f, 0.f, 0.f);
            if (gr < N)
                v = ((const float4*)x)[(size_t)gr * (FIN / 4) + kt * 8 + c4];
            float* dp = &xs[r * 33 + c4 * 4];
            dp[0] = v.x; dp[1] = v.y; dp[2] = v.z; dp[3] = v.w;
        }
        __syncthreads();

        const ulonglong2* Wp = (const ulonglong2*)(Ws + (size_t)kt * 32 * HID);
        #pragma unroll
        for (int c = 0; c < 32; c++) {
            float xv = xs[tid * 33 + c];
            unsigned long long x2;
            asm("mov.b64 %0,{%1,%1};" : "=l"(x2) : "f"(xv));
            #pragma unroll
            for (int j = 0; j < 4; j++) {
                ulonglong2 w = Wp[c * 4 + j];
                asm("fma.rn.f32x2 %0,%1,%2,%0;" : "+l"(acc[2*j])   : "l"(x2), "l"(w.x));
                asm("fma.rn.f32x2 %0,%1,%2,%0;" : "+l"(acc[2*j+1]) : "l"(x2), "l"(w.y));
            }
        }
    }

    if (row < N) {
        float4* hp = (float4*)(d_h1p + (size_t)row * HID);
        #pragma unroll
        for (int j = 0; j < HID / 2; j++) {
            float lo, hi;
            asm("mov.b64 {%0,%1},%2;" : "=f"(lo), "=f"(hi) : "l"(acc[j]));
            ((float*)hp)[2*j]   = lo;
            ((float*)hp)[2*j+1] = hi;
        }
    }
}

// scale messages: h1p[i] *= dinv[i]  (thread per float4)
__global__ void k_scale(int N4) {
    int t = blockIdx.x * blockDim.x + threadIdx.x;
    if (t >= N4) return;
    float dv = d_dinv[t >> 2];
    float4* p = (float4*)d_h1p + t;
    float4 v = *p;
    v.x *= dv; v.y *= dv; v.z *= dv; v.w *= dv;
    *p = v;
}

// Layer-1 aggregation + fused layer-2 MLP. One warp per node.
// 4 lanes per edge (one float4 each); next-index prefetch hides idx latency.
__global__ void __launch_bounds__(256) k_agg1(const float* __restrict__ b1,
                                              const float* __restrict__ W2,
                                              int N) {
    int warp = (blockIdx.x * blockDim.x + threadIdx.x) >> 5;
    if (warp >= N) return;
    int lane = threadIdx.x & 31;
    int p = lane & 3;
    int base = __ldg(&d_rs[warp]);
    int end  = base + __ldg(&d_cnt[warp]);

    float4 acc = make_float4(0.f, 0.f, 0.f, 0.f);
    int it = base + (lane >> 2);
    bool ok = it < end;
    int s = ok ? __ldg(&d_csr[it]) : 0;
    while (ok) {
        int it1 = it + 8;
        bool ok1 = it1 < end;
        int s1 = ok1 ? __ldg(&d_csr[it1]) : 0;       // prefetch next index
        float4 v = __ldg(&((const float4*)d_h1p)[(size_t)s * 4 + p]);
        acc.x += v.x; acc.y += v.y; acc.z += v.z; acc.w += v.w;
        s = s1; it = it1; ok = ok1;
    }
    __syncwarp();
    #pragma unroll
    for (int off = 16; off >= 4; off >>= 1) {
        acc.x += __shfl_down_sync(0xffffffffu, acc.x, off);
        acc.y += __shfl_down_sync(0xffffffffu, acc.y, off);
        acc.z += __shfl_down_sync(0xffffffffu, acc.z, off);
        acc.w += __shfl_down_sync(0xffffffffu, acc.w, off);
    }
    if (lane < 4) {
        float dv = d_dinv[warp];
        float4 self = ((const float4*)d_h1p)[warp * 4 + lane];  // already scaled
        acc.x += self.x; acc.y += self.y; acc.z += self.z; acc.w += self.w;
        float4 bb = __ldg(&((const float4*)b1)[lane]);
        float4 w  = __ldg(&((const float4*)W2)[lane]);
        float g = fmaxf(fmaf(dv, acc.x, bb.x), 0.f) * w.x
                + fmaxf(fmaf(dv, acc.y, bb.y), 0.f) * w.y
                + fmaxf(fmaf(dv, acc.z, bb.z), 0.f) * w.z
                + fmaxf(fmaf(dv, acc.w, bb.w), 0.f) * w.w;
        g += __shfl_xor_sync(0xfu, g, 1);
        g += __shfl_xor_sync(0xfu, g, 2);
        if (lane == 0) d_gp[warp] = g * dv;
    }
}

// Layer-2 aggregation + sigmoid. One warp per node, scalar gathers.
__global__ void __launch_bounds__(256) k_agg2(const float* __restrict__ b2,
                                              float* __restrict__ out, int N) {
    int warp = (blockIdx.x * blockDim.x + threadIdx.x) >> 5;
    if (warp >= N) return;
    int lane = threadIdx.x & 31;
    int base = __ldg(&d_rs[warp]);
    int end  = base + __ldg(&d_cnt[warp]);

    float sum = 0.f;
    for (int j = base + lane; j < end; j += 32)
        sum += __ldg(&d_gp[__ldg(&d_csr[j])]);
    __syncwarp();
    #pragma unroll
    for (int off = 16; off >= 1; off >>= 1)
        sum += __shfl_down_sync(0xffffffffu, sum, off);
    if (lane == 0) {
        float dv = d_dinv[warp];
        float z = fmaf(dv, sum + d_gp[warp], __ldg(&b2[0]));
        out[warp] = 1.f / (1.f + __expf(-z));
    }
}

// ---------------- launch ----------------
extern "C" void kernel_launch(void* const* d_in, const int* in_sizes, int n_in,
                              void* d_out, int out_size) {
    const float* x  = (const float*)d_in[0];
    const float* W1 = (const float*)d_in[1];
    const float* b1 = (const float*)d_in[2];
    const float* W2 = (const float*)d_in[3];
    const float* b2 = (const float*)d_in[4];
    const int*   ei = (const int*)d_in[5];

    int N = in_sizes[0] / FIN;     // 100000
    int E = in_sizes[5] / 2;       // 3200000
    int NB = (N + SCAN_BS - 1) / SCAN_BS;

    static cudaStream_t s2 = nullptr;
    static cudaEvent_t evA = nullptr, evB = nullptr;
    if (!s2) {
        cudaStreamCreateWithFlags(&s2, cudaStreamNonBlocking);
        cudaEventCreateWithFlags(&evA, cudaEventDisableTiming);
        cudaEventCreateWithFlags(&evB, cudaEventDisableTiming);
        const int SMEM_BYTES = (FIN * HID + 256 * 33) * (int)sizeof(float);
        cudaFuncSetAttribute(k_gemm, cudaFuncAttributeMaxDynamicSharedMemorySize,
                             SMEM_BYTES);
    }
    const int SMEM_BYTES = (FIN * HID + 256 * 33) * (int)sizeof(float); // 66560

    // fork AT CAPTURE START: gemm has zero dependencies now.
    cudaEventRecord(evA, 0);
    cudaStreamWaitEvent(s2, evA, 0);

    // main stream: CSR build (fully independent of gemm)
    k_zero   <<<(N + 255) / 256, 256>>>(N);
    k_deg    <<<((E / 4) + 255) / 256, 256>>>(ei + E, E);
    k_scanA  <<<NB, SCAN_BS>>>(N);
    k_gemm   <<<(N + 255) / 256, 256, SMEM_BYTES, s2>>>(x, W1, N);   // 4th submit
    k_scanFix<<<(N + 255) / 256, 256>>>(N);
    k_fill   <<<((E / 4) + 255) / 256, 256>>>(ei, E);
    cudaEventRecord(evB, s2);

    // join, then scale + aggregate
    cudaStreamWaitEvent(0, evB, 0);
    k_scale<<<(N * 4 + 255) / 256, 256>>>(N * 4);
    k_agg1 <<<(N * 32 + 255) / 256, 256>>>(b1, W2, N);
    k_agg2 <<<(N * 32 + 255) / 256, 256>>>(b2, (float*)d_out, N);
}

// round 4
// speedup vs baseline: 1.0499x; 1.0201x over previous
#include <cuda_runtime.h>

#define NMAX 100000
#define EMAX 3200000
#define FIN  512
#define HID  16
#define SCAN_BS 1024
#define SCAN_NBMAX 128

// ---------------- scratch (static device globals; no allocs) ----------------
__device__ int   d_cnt [NMAX];          // edge count per dst (excl self-loop)
__device__ float d_dinv[NMAX];          // (deg+1)^-1/2
__device__ float d_h1p [NMAX * HID];    // h1 (then scaled by dinv[src])
__device__ float d_gp  [NMAX];          // g * dinv[src] for layer 2
__device__ int   d_rs  [NMAX];          // CSR row starts (by dst)
__device__ int   d_next[NMAX];          // fill cursors
__device__ int   d_csr [EMAX];          // src ids grouped by dst
__device__ int   d_bsum[SCAN_NBMAX];

// ---------------- kernels ----------------
__global__ void k_zero(int N) {
    int i = blockIdx.x * blockDim.x + threadIdx.x;
    if (i < N) d_cnt[i] = 0;
}

__global__ void k_deg(const int* __restrict__ dst, int E) {
    int t = blockIdx.x * blockDim.x + threadIdx.x;
    int e4 = t * 4;
    if (e4 + 3 < E) {
        int4 d = __ldg(&((const int4*)dst)[t]);
        atomicAdd(&d_cnt[d.x], 1);
        atomicAdd(&d_cnt[d.y], 1);
        atomicAdd(&d_cnt[d.z], 1);
        atomicAdd(&d_cnt[d.w], 1);
    } else {
        for (int e = e4; e < E; e++) atomicAdd(&d_cnt[dst[e]], 1);
    }
}

__global__ void __launch_bounds__(SCAN_BS) k_scanA(int N) {
    int i = blockIdx.x * SCAN_BS + threadIdx.x;
    int lane = threadIdx.x & 31, w = threadIdx.x >> 5;
    int c = (i < N) ? d_cnt[i] : 0;
    int v = c;
    #pragma unroll
    for (int off = 1; off < 32; off <<= 1) {
        int n = __shfl_up_sync(0xffffffffu, v, off);
        if (lane >= off) v += n;
    }
    __shared__ int ws[32];
    if (lane == 31) ws[w] = v;
    __syncthreads();
    if (w == 0) {
        int s = ws[lane];
        #pragma unroll
        for (int off = 1; off < 32; off <<= 1) {
            int n = __shfl_up_sync(0xffffffffu, s, off);
            if (lane >= off) s += n;
        }
        ws[lane] = s;
    }
    __syncthreads();
    int add = w ? ws[w - 1] : 0;
    if (i < N) d_rs[i] = add + v - c;
    if (threadIdx.x == SCAN_BS - 1) d_bsum[blockIdx.x] = add + v;
}

// GEMM1: h1 = x @ W1, 2 rows/thread register tiling. 128 thr, 256 rows/block.
__global__ void __launch_bounds__(128) k_gemm(const float* __restrict__ x,
                                              const float* __restrict__ W1,
                                              int N) {
    extern __shared__ float sm[];
    float* Ws = sm;                  // FIN*HID = 8192 floats (32KB)
    float* xs = sm + FIN * HID;      // 256 rows * 33 floats (pad)
    int tid = threadIdx.x;

    {   // stage W1 (coalesced): 16 float4 per thread
        const float4* W4 = (const float4*)W1;
        float4*       Wd = (float4*)Ws;
        #pragma unroll
        for (int i = 0; i < 16; i++)
            Wd[tid + i * 128] = W4[tid + i * 128];
    }

    int rbase = blockIdx.x * 256;
    unsigned long long a0[HID / 2], a1[HID / 2];
    #pragma unroll
    for (int j = 0; j < HID / 2; j++) { a0[j] = 0ull; a1[j] = 0ull; }

    for (int kt = 0; kt < FIN / 32; kt++) {
        __syncthreads();
        // stage 256 rows x 32 k: 16 float4 per thread, 8 lanes span one row
        #pragma unroll
        for (int i = 0; i < 16; i++) {
            int fid = tid + i * 128;
            int r = fid >> 3, c4 = fid & 7;
            int gr = rbase + r;
            float4 v = make_float4(0.f, 0.f, 0.f, 0.f);
            if (gr < N)
                v = ((const float4*)x)[(size_t)gr * (FIN / 4) + kt * 8 + c4];
            float* dp = &xs[r * 33 + c4 * 4];
            dp[0] = v.x; dp[1] = v.y; dp[2] = v.z; dp[3] = v.w;
        }
        __syncthreads();

        const ulonglong2* Wp = (const ulonglong2*)(Ws + (size_t)kt * 32 * HID);
        #pragma unroll
        for (int c = 0; c < 32; c++) {
            float x0 = xs[tid * 33 + c];
            float x1 = xs[(tid + 128) * 33 + c];
            unsigned long long X0, X1;
            asm("mov.b64 %0,{%1,%1};" : "=l"(X0) : "f"(x0));
            asm("mov.b64 %0,{%1,%1};" : "=l"(X1) : "f"(x1));
            #pragma unroll
            for (int j = 0; j < 4; j++) {
                ulonglong2 w = Wp[c * 4 + j];   // one LDS.128 feeds 4 FFMA2
                asm("fma.rn.f32x2 %0,%1,%2,%0;" : "+l"(a0[2*j])   : "l"(X0), "l"(w.x));
                asm("fma.rn.f32x2 %0,%1,%2,%0;" : "+l"(a0[2*j+1]) : "l"(X0), "l"(w.y));
                asm("fma.rn.f32x2 %0,%1,%2,%0;" : "+l"(a1[2*j])   : "l"(X1), "l"(w.x));
                asm("fma.rn.f32x2 %0,%1,%2,%0;" : "+l"(a1[2*j+1]) : "l"(X1), "l"(w.y));
            }
        }
    }

    int row0 = rbase + tid, row1 = row0 + 128;
    if (row0 < N) {
        float* hp = d_h1p + (size_t)row0 * HID;
        #pragma unroll
        for (int j = 0; j < HID / 2; j++)
            asm("mov.b64 {%0,%1},%2;" : "=f"(hp[2*j]), "=f"(hp[2*j+1]) : "l"(a0[j]));
    }
    if (row1 < N) {
        float* hp = d_h1p + (size_t)row1 * HID;
        #pragma unroll
        for (int j = 0; j < HID / 2; j++)
            asm("mov.b64 {%0,%1},%2;" : "=f"(hp[2*j]), "=f"(hp[2*j+1]) : "l"(a1[j]));
    }
}

// fuse scanB+scanC: add prefix of block sums; set dinv + cursors.
__global__ void __launch_bounds__(256) k_scanFix(int N) {
    __shared__ int wsum[8];
    __shared__ int s_off;
    int t = threadIdx.x;
    int nb = blockIdx.x >> 2;
    int v = (t < nb && t < SCAN_NBMAX) ? d_bsum[t] : 0;
    #pragma unroll
    for (int off = 16; off >= 1; off >>= 1)
        v += __shfl_down_sync(0xffffffffu, v, off);
    if ((t & 31) == 0) wsum[t >> 5] = v;
    __syncthreads();
    if (t == 0) {
        int s = 0;
        #pragma unroll
        for (int k = 0; k < 8; k++) s += wsum[k];
        s_off = s;
    }
    __syncthreads();
    int i = blockIdx.x * 256 + t;
    if (i < N) {
        int r = d_rs[i] + s_off;
        d_rs[i]   = r;
        d_next[i] = r;
        d_dinv[i] = rsqrtf((float)(d_cnt[i] + 1));
    }
}

__global__ void k_fill(const int* __restrict__ ei, int E) {
    int t = blockIdx.x * blockDim.x + threadIdx.x;
    int e4 = t * 4;
    if (e4 + 3 < E) {
        int4 s = __ldg(&((const int4*)ei)[t]);
        int4 d = __ldg(&((const int4*)(ei + E))[t]);
        d_csr[atomicAdd(&d_next[d.x], 1)] = s.x;
        d_csr[atomicAdd(&d_next[d.y], 1)] = s.y;
        d_csr[atomicAdd(&d_next[d.z], 1)] = s.z;
        d_csr[atomicAdd(&d_next[d.w], 1)] = s.w;
    } else {
        for (int e = e4; e < E; e++)
            d_csr[atomicAdd(&d_next[ei[E + e]], 1)] = ei[e];
    }
}

// scale messages: h1p[i] *= dinv[i]
__global__ void k_scale(int N4) {
    int t = blockIdx.x * blockDim.x + threadIdx.x;
    if (t >= N4) return;
    float dv = d_dinv[t >> 2];
    float4* p = (float4*)d_h1p + t;
    float4 v = *p;
    v.x *= dv; v.y *= dv; v.z *= dv; v.w *= dv;
    *p = v;
}

// Layer-1 aggregation + fused layer-2 MLP. One warp per node.
__global__ void __launch_bounds__(256) k_agg1(const float* __restrict__ b1,
                                              const float* __restrict__ W2,
                                              int N) {
    int warp = (blockIdx.x * blockDim.x + threadIdx.x) >> 5;
    if (warp >= N) return;
    int lane = threadIdx.x & 31;
    int p = lane & 3;
    int base = __ldg(&d_rs[warp]);
    int end  = base + __ldg(&d_cnt[warp]);

    float4 acc = make_float4(0.f, 0.f, 0.f, 0.f);
    int it = base + (lane >> 2);
    bool ok = it < end;
    int s = ok ? __ldg(&d_csr[it]) : 0;
    while (ok) {
        int it1 = it + 8;
        bool ok1 = it1 < end;
        int s1 = ok1 ? __ldg(&d_csr[it1]) : 0;
        float4 v = __ldg(&((const float4*)d_h1p)[(size_t)s * 4 + p]);
        acc.x += v.x; acc.y += v.y; acc.z += v.z; acc.w += v.w;
        s = s1; it = it1; ok = ok1;
    }
    __syncwarp();
    #pragma unroll
    for (int off = 16; off >= 4; off >>= 1) {
        acc.x += __shfl_down_sync(0xffffffffu, acc.x, off);
        acc.y += __shfl_down_sync(0xffffffffu, acc.y, off);
        acc.z += __shfl_down_sync(0xffffffffu, acc.z, off);
        acc.w += __shfl_down_sync(0xffffffffu, acc.w, off);
    }
    if (lane < 4) {
        float dv = d_dinv[warp];
        float4 self = ((const float4*)d_h1p)[warp * 4 + lane];
        acc.x += self.x; acc.y += self.y; acc.z += self.z; acc.w += self.w;
        float4 bb = __ldg(&((const float4*)b1)[lane]);
        float4 w  = __ldg(&((const float4*)W2)[lane]);
        float g = fmaxf(fmaf(dv, acc.x, bb.x), 0.f) * w.x
                + fmaxf(fmaf(dv, acc.y, bb.y), 0.f) * w.y
                + fmaxf(fmaf(dv, acc.z, bb.z), 0.f) * w.z
                + fmaxf(fmaf(dv, acc.w, bb.w), 0.f) * w.w;
        g += __shfl_xor_sync(0xfu, g, 1);
        g += __shfl_xor_sync(0xfu, g, 2);
        if (lane == 0) d_gp[warp] = g * dv;
    }
}

// Layer-2 aggregation + sigmoid. One warp per node.
__global__ void __launch_bounds__(256) k_agg2(const float* __restrict__ b2,
                                              float* __restrict__ out, int N) {
    int warp = (blockIdx.x * blockDim.x + threadIdx.x) >> 5;
    if (warp >= N) return;
    int lane = threadIdx.x & 31;
    int base = __ldg(&d_rs[warp]);
    int end  = base + __ldg(&d_cnt[warp]);

    float sum = 0.f;
    for (int j = base + lane; j < end; j += 32)
        sum += __ldg(&d_gp[__ldg(&d_csr[j])]);
    __syncwarp();
    #pragma unroll
    for (int off = 16; off >= 1; off >>= 1)
        sum += __shfl_down_sync(0xffffffffu, sum, off);
    if (lane == 0) {
        float dv = d_dinv[warp];
        float z = fmaf(dv, sum + d_gp[warp], __ldg(&b2[0]));
        out[warp] = 1.f / (1.f + __expf(-z));
    }
}

// ---------------- launch ----------------
extern "C" void kernel_launch(void* const* d_in, const int* in_sizes, int n_in,
                              void* d_out, int out_size) {
    const float* x  = (const float*)d_in[0];
    const float* W1 = (const float*)d_in[1];
    const float* b1 = (const float*)d_in[2];
    const float* W2 = (const float*)d_in[3];
    const float* b2 = (const float*)d_in[4];
    const int*   ei = (const int*)d_in[5];

    int N = in_sizes[0] / FIN;     // 100000
    int E = in_sizes[5] / 2;       // 3200000
    int NB = (N + SCAN_BS - 1) / SCAN_BS;

    static cudaStream_t s2 = nullptr;
    static cudaEvent_t evA = nullptr, evB = nullptr;
    if (!s2) {
        cudaStreamCreateWithFlags(&s2, cudaStreamNonBlocking);
        cudaEventCreateWithFlags(&evA, cudaEventDisableTiming);
        cudaEventCreateWithFlags(&evB, cudaEventDisableTiming);
        const int SMEM_BYTES = (FIN * HID + 256 * 33) * (int)sizeof(float);
        cudaFuncSetAttribute(k_gemm, cudaFuncAttributeMaxDynamicSharedMemorySize,
                             SMEM_BYTES);
    }
    const int SMEM_BYTES = (FIN * HID + 256 * 33) * (int)sizeof(float); // 66560

    // fork at capture start: gemm has zero dependencies.
    cudaEventRecord(evA, 0);
    cudaStreamWaitEvent(s2, evA, 0);

    // main stream: CSR build
    k_zero   <<<(N + 255) / 256, 256>>>(N);
    k_deg    <<<((E / 4) + 255) / 256, 256>>>(ei + E, E);
    k_scanA  <<<NB, SCAN_BS>>>(N);
    k_gemm   <<<(N + 255) / 256, 128, SMEM_BYTES, s2>>>(x, W1, N);  // 4th submit
    k_scanFix<<<(N + 255) / 256, 256>>>(N);
    k_fill   <<<((E / 4) + 255) / 256, 256>>>(ei, E);
    cudaEventRecord(evB, s2);

    cudaStreamWaitEvent(0, evB, 0);
    k_scale<<<(N * 4 + 255) / 256, 256>>>(N * 4);
    k_agg1 <<<(N * 32 + 255) / 256, 256>>>(b1, W2, N);
    k_agg2 <<<(N * 32 + 255) / 256, 256>>>(b2, (float*)d_out, N);
}